// round 17
// baseline (speedup 1.0000x reference)
#include <cuda_runtime.h>
#include <math_constants.h>
#include <cfloat>

// Problem constants (B=2, L=256, A=12, C=32, K=30)
#define NB 2
#define NL 256
#define NA 12
#define NATOM 3072          // NL*NA
#define NROWS (NB*NATOM)    // 6144
#define NC 32
#define KNB 30
#define BIGD 1000000.0f
#define EMPTY_BITS 0xFFFFFFFFu
#define POISON 1.0e18f               // masked-atom coordinate (d2 -> 3e36 exactly)
#define FULL 0xffffffffu

// Output layout (all float32, concatenated in reference tuple order)
#define O_COORDS 0                       // (B, NATOM, 3)  -> 18432
#define O_MASK   (NB*NATOM*3)            // (B, NATOM)     -> 6144
#define O_ENC    (O_MASK + NB*NATOM)     // (B, NATOM, 32) -> 196608
#define O_DIST   (O_ENC + NB*NATOM*NC)   // (B, NATOM, 30) -> 184320
#define O_IDX    (O_DIST + NB*NATOM*KNB) // (B, NATOM, 30) -> 184320

#define WARPS 4              // row slots per block (1 row per warp)
#define THR (WARPS * 32)     // 128

// Compacted per-batch atom table: actives first (ascending index), masked
// (poisoned coords) after. .w = atom index within batch, as float (exact).
__device__ float4 g_cat[NB * NATOM];
__device__ float  g_A[NB * NC];          // rstd * scale
__device__ float  g_B[NB * NC];          // shift - mean * rstd * scale
__device__ int    g_rows[NROWS];         // query compaction: active rows first
__device__ int    g_nact;                // active rows (global)
__device__ int    g_nactb[NB];           // active atoms per batch

// ---------------------------------------------------------------------------
// Prep (unchanged from R15): each block recomputes the residue scan, places
// its 256 atoms into g_cat / g_rows; block 0 writes coefs + counters.
// ---------------------------------------------------------------------------
#define PREP_BLOCKS 24
__global__ void prep_kernel(const float* __restrict__ coords,
                            const int* __restrict__ mask,
                            const float* __restrict__ T,
                            const float* __restrict__ scale,
                            const float* __restrict__ shift) {
    __shared__ int s_mask[NB * NL];
    __shared__ int s_lanepre[33];

    int tid = threadIdx.x;                // 256

    if (tid < 32) {
        int mloc[16];
        int s = 0;
        #pragma unroll
        for (int i = 0; i < 16; ++i) {
            mloc[i] = mask[tid * 16 + i];
            s_mask[tid * 16 + i] = mloc[i];
            s += mloc[i];
        }
        int incl = s;
        #pragma unroll
        for (int off = 1; off < 32; off <<= 1) {
            int v = __shfl_up_sync(FULL, incl, off);
            if (tid >= off) incl += v;
        }
        s_lanepre[tid] = incl - s;
        if (tid == 31) s_lanepre[32] = incl;
    }
    __syncthreads();

    int nAg = s_lanepre[32];
    int nA0 = s_lanepre[16];
    int nA1 = nAg - nA0;

    if (blockIdx.x == 0) {
        if (tid == 0) {
            g_nact = nAg * NA;
            g_nactb[0] = nA0 * NA;
            g_nactb[1] = nA1 * NA;
        }
        if (tid < NB * NC) {
            int b = tid >> 5, c = tid & 31;
            float nm = (float)(b ? nA1 : nA0);
            float colsum = 0.f, tv[NA];
            #pragma unroll
            for (int a = 0; a < NA; ++a) { tv[a] = T[a * NC + c]; colsum += tv[a]; }
            float cntA = nm * (float)NA;
            float cnt  = fmaxf(cntA, 1.0f);
            float mean = (nm * colsum) / cnt;
            float ssqm = 0.f;
            #pragma unroll
            for (int a = 0; a < NA; ++a) {
                float d = tv[a] - mean;
                ssqm = fmaf(d, d, ssqm);
            }
            float ssq  = nm * ssqm + ((float)NATOM - cntA) * mean * mean;
            float rstd = rsqrtf(ssq / cnt + 1e-5f);
            float Ac   = rstd * scale[c];
            g_A[tid] = Ac;
            g_B[tid] = shift[c] - mean * Ac;
        }
    }

    int a  = blockIdx.x * 256 + tid;
    int b  = a / NATOM;
    int j  = a - b * NATOM;
    int rb = j / NA;
    int ty = j - rb * NA;
    int r  = b * NL + rb;
    int l  = r >> 4, loc = r & 15;
    int pre = s_lanepre[l];
    for (int i = 0; i < loc; ++i) pre += s_mask[l * 16 + i];
    int m = s_mask[r];

    int preB = pre - (b ? nA0 : 0);
    int nAb  = b ? nA1 : nA0;
    int pos  = m ? (NA * preB + ty)
                 : (NA * (nAb + (rb - preB)) + ty);
    float x = coords[a * 3 + 0], y = coords[a * 3 + 1], z = coords[a * 3 + 2];
    float4 v;
    v.x = m ? x : POISON;
    v.y = m ? y : POISON;
    v.z = m ? z : POISON;
    v.w = (float)j;
    g_cat[b * NATOM + pos] = v;

    int slot = m ? (NA * pre + ty)
                 : (NA * (nAg + (r - pre)) + ty);
    g_rows[slot] = a;
}

// ---------------------------------------------------------------------------
// Cooperative refill (slow path): k-th smallest over positions [t0,t1) of
// column w (t1-t0 <= 48 -> 2 rounds needed, 3 coded). q warp-uniform.
// ---------------------------------------------------------------------------
__device__ __forceinline__ void refillR(const float4* At, int lane, int w,
                                        int t0, int t1, int k,
                                        float qx, float qy, float qz,
                                        unsigned &resv, int &resj) {
    unsigned kv[3]; int kj[3];
    #pragma unroll
    for (int s = 0; s < 3; ++s) {
        int t = t0 + s * 32 + lane;
        if (t < t1) {
            float4 a = __ldg(&At[t * 32 + w]);
            float dx = qx - a.x, dy = qy - a.y, dz = qz - a.z;
            kv[s] = __float_as_uint(fmaf(dx, dx, fmaf(dy, dy, dz * dz)));
            kj[s] = t * 32 + w;
        } else { kv[s] = EMPTY_BITS; kj[s] = 0x7fffffff; }
    }
    resv = EMPTY_BITS; resj = 0;
    for (int it = 0; it < k; ++it) {
        unsigned lm = kv[0]; int lj = kj[0];
        if (kv[1] < lm) { lm = kv[1]; lj = kj[1]; }
        if (kv[2] < lm) { lm = kv[2]; lj = kj[2]; }
        unsigned gm  = __reduce_min_sync(FULL, lm);
        unsigned gcj = (lm == gm) ? (unsigned)lj : 0xFFFFFFFFu;
        unsigned gj  = __reduce_min_sync(FULL, gcj);
        resv = gm; resj = (int)gj;
        if (kj[0] == (int)gj) kv[0] = EMPTY_BITS;
        if (kj[1] == (int)gj) kv[1] = EMPTY_BITS;
        if (kj[2] == (int)gj) kv[2] = EMPTY_BITS;
    }
}

// ---------------------------------------------------------------------------
// Exact slow path (R15 engine, tie-safe). Rewrites all 30 outputs of a row.
// ---------------------------------------------------------------------------
__device__ __noinline__ void slow_row(const float4* At, int lane,
                                      int mid, int Tn,
                                      float qx, float qy, float qz,
                                      float* dist_out, float* idx_out) {
    unsigned va0 = EMPTY_BITS, va1 = EMPTY_BITS, vb0 = EMPTY_BITS, vb1 = EMPTY_BITS;
    int ia0 = 0, ia1 = 0, ib0 = 0, ib1 = 0;

    for (int t = 0; t < mid; ++t) {
        float4 a = __ldg(&At[t * 32 + lane]);
        float dx = qx - a.x, dy = qy - a.y, dz = qz - a.z;
        unsigned kb = __float_as_uint(fmaf(dx, dx, fmaf(dy, dy, dz * dz)));
        int j = t * 32 + lane;
        bool lt1 = kb < va1, lt0 = kb < va0;
        va1 = lt1 ? (lt0 ? va0 : kb) : va1;
        ia1 = lt1 ? (lt0 ? ia0 : j ) : ia1;
        va0 = lt0 ? kb : va0;
        ia0 = lt0 ? j  : ia0;
    }
    for (int t = mid; t < Tn; ++t) {
        float4 a = __ldg(&At[t * 32 + lane]);
        float dx = qx - a.x, dy = qy - a.y, dz = qz - a.z;
        unsigned kb = __float_as_uint(fmaf(dx, dx, fmaf(dy, dy, dz * dz)));
        int j = t * 32 + lane;
        bool lt1 = kb < vb1, lt0 = kb < vb0;
        vb1 = lt1 ? (lt0 ? vb0 : kb) : vb1;
        ib1 = lt1 ? (lt0 ? ib0 : j ) : ib1;
        vb0 = lt0 ? kb : vb0;
        ib0 = lt0 ? j  : ib0;
    }

    int cA = 0, cB = 0;
    unsigned rvb = EMPTY_BITS; int rj = 0;

    for (int p = 0; p < KNB; ++p) {
        unsigned pv = (vb0 < va0) ? vb0 : va0;   // tie -> A (lower positions)
        int      pi = (vb0 < va0) ? ib0 : ia0;

        unsigned mvb = __reduce_min_sync(FULL, pv);
        unsigned cj  = (pv == mvb) ? (unsigned)pi : 0xFFFFFFFFu;
        unsigned mj  = __reduce_min_sync(FULL, cj);
        if (lane == p) { rvb = mvb; rj = (int)mj; }

        if (p < KNB - 1) {
            int w  = (int)(mj & 31u);
            int tm = (int)(mj >> 5);
            bool fromA = (tm < mid);
            bool needRefill = false;
            if (lane == w) {
                if (fromA) { va0 = va1; ia0 = ia1; va1 = EMPTY_BITS; ++cA;
                             needRefill = (va0 == EMPTY_BITS); }
                else       { vb0 = vb1; ib0 = ib1; vb1 = EMPTY_BITS; ++cB;
                             needRefill = (vb0 == EMPTY_BITS); }
            }
            if (__ballot_sync(FULL, needRefill)) {
                int k = __shfl_sync(FULL, fromA ? cA : cB, w) + 1;
                unsigned resv; int resj;
                refillR(At, lane, w, fromA ? 0 : mid, fromA ? mid : Tn, k,
                        qx, qy, qz, resv, resj);
                if (lane == w) {
                    if (fromA) { va0 = resv; ia0 = resj; }
                    else       { vb0 = resv; ib0 = resj; }
                }
            }
        }
    }

    if (lane < KNB) {
        float d2 = __uint_as_float(rvb);
        dist_out[lane] = (d2 > 1e30f) ? BIGD : sqrtf(d2 + 1e-6f);
        idx_out[lane]  = __ldg(&At[rj]).w;
    }
}

// ---------------------------------------------------------------------------
// KNN fast path: single-redux extraction, owner self-identifies (unique keys),
// writes results directly, solo register-bitmask refill. Tie anomaly detected
// by pop-count check -> exact slow-path rerun.
// ---------------------------------------------------------------------------
__global__ void __launch_bounds__(THR, 8)
knn_kernel(const float* __restrict__ coords,
           const int* __restrict__ mask,
           const float* __restrict__ T,
           float* __restrict__ out) {
    int tid  = threadIdx.x;
    int warp = tid >> 5;
    int lane = tid & 31;

    // coords copy + mask output, spread over grid threads
    {
        int i = blockIdx.x * THR + tid;
        if (i < NROWS * 3) out[O_COORDS + i] = coords[i];
        if (i < NROWS) {
            int bb = i / NATOM;
            int jj = i - bb * NATOM;
            out[O_MASK + i] = (float)mask[bb * NL + jj / NA];
        }
    }

    int slot = blockIdx.x * WARPS + warp;
    int row  = g_rows[slot];
    int b    = row / NATOM;

    float* dist_out = out + O_DIST + row * KNB;
    float* idx_out  = out + O_IDX  + row * KNB;

    if (slot >= g_nact) {                     // masked row -> constant outputs
        out[O_ENC + row * NC + lane] = 0.0f;
        if (lane < KNB) {
            dist_out[lane] = BIGD;
            idx_out[lane]  = 0.0f;
        }
        return;
    }

    int ib = row - b * NATOM;
    const float4* At = g_cat + b * NATOM;

    float qx = __ldg(&coords[row * 3 + 0]);
    float qy = __ldg(&coords[row * 3 + 1]);
    float qz = __ldg(&coords[row * 3 + 2]);

    // encode for active row
    {
        int ty = ib % NA;
        out[O_ENC + row * NC + lane] =
            fmaf(__ldg(&T[ty * NC + lane]), g_A[b * NC + lane], g_B[b * NC + lane]);
    }

    int nact_b = g_nactb[b];
    int Tn = ((nact_b + 31) >> 5) + 1;        // +1 poisoned window
    if (Tn > 96) Tn = 96;
    int mid = (Tn + 1) >> 1;                  // stream split (both <= 48 windows)

    // ---- phase A: two branchless top-2 streams per lane ----
    unsigned va0 = EMPTY_BITS, va1 = EMPTY_BITS, vb0 = EMPTY_BITS, vb1 = EMPTY_BITS;
    int ia0 = 0, ia1 = 0, ib0 = 0, ib1 = 0;

    #pragma unroll 4
    for (int t = 0; t < mid; ++t) {
        float4 a = __ldg(&At[t * 32 + lane]);
        float dx = qx - a.x, dy = qy - a.y, dz = qz - a.z;
        unsigned kb = __float_as_uint(fmaf(dx, dx, fmaf(dy, dy, dz * dz)));
        int j = t * 32 + lane;
        bool lt1 = kb < va1, lt0 = kb < va0;  // strict < keeps lowest-pos ties
        va1 = lt1 ? (lt0 ? va0 : kb) : va1;
        ia1 = lt1 ? (lt0 ? ia0 : j ) : ia1;
        va0 = lt0 ? kb : va0;
        ia0 = lt0 ? j  : ia0;
    }
    #pragma unroll 4
    for (int t = mid; t < Tn; ++t) {
        float4 a = __ldg(&At[t * 32 + lane]);
        float dx = qx - a.x, dy = qy - a.y, dz = qz - a.z;
        unsigned kb = __float_as_uint(fmaf(dx, dx, fmaf(dy, dy, dz * dz)));
        int j = t * 32 + lane;
        bool lt1 = kb < vb1, lt0 = kb < vb0;
        vb1 = lt1 ? (lt0 ? vb0 : kb) : vb1;
        ib1 = lt1 ? (lt0 ? ib0 : j ) : ib1;
        vb0 = lt0 ? kb : vb0;
        ib0 = lt0 ? j  : ib0;
    }

    // ---- fast extraction: 1 redux per pass; owner self-identifies ----
    unsigned long long popA = 0ull, popB = 0ull;  // popped windows (per stream)
    int npop = 0;

    #pragma unroll 1
    for (int p = 0; p < KNB; ++p) {
        bool useB = (vb0 < va0);              // tie -> A (lower positions)
        unsigned pv = useB ? vb0 : va0;
        int      pi = useB ? ib0 : ia0;

        unsigned mvb = __reduce_min_sync(FULL, pv);
        if (pv == mvb) {                      // owner (unique keys assumed)
            float d2 = __uint_as_float(mvb);
            dist_out[p] = (d2 > 1e30f) ? BIGD : sqrtf(d2 + 1e-6f);
            idx_out[p]  = __ldg(&At[pi]).w;
            ++npop;
            if (p < KNB - 1) {
                int tm = pi >> 5;
                if (useB) {
                    popB |= 1ull << (tm - mid);
                    vb0 = vb1; ib0 = ib1; vb1 = EMPTY_BITS;
                    if (vb0 == EMPTY_BITS) {  // solo refill stream B
                        unsigned best = EMPTY_BITS; int bj2 = 0;
                        for (int t = mid; t < Tn; ++t) {
                            float4 a = __ldg(&At[t * 32 + lane]);
                            float dx = qx - a.x, dy = qy - a.y, dz = qz - a.z;
                            unsigned kb = __float_as_uint(
                                fmaf(dx, dx, fmaf(dy, dy, dz * dz)));
                            bool ok = !((popB >> (t - mid)) & 1ull) && (kb < best);
                            best = ok ? kb : best;
                            bj2  = ok ? t * 32 + lane : bj2;
                        }
                        vb0 = best; ib0 = bj2;
                    }
                } else {
                    popA |= 1ull << tm;
                    va0 = va1; ia0 = ia1; va1 = EMPTY_BITS;
                    if (va0 == EMPTY_BITS) {  // solo refill stream A
                        unsigned best = EMPTY_BITS; int bj2 = 0;
                        for (int t = 0; t < mid; ++t) {
                            float4 a = __ldg(&At[t * 32 + lane]);
                            float dx = qx - a.x, dy = qy - a.y, dz = qz - a.z;
                            unsigned kb = __float_as_uint(
                                fmaf(dx, dx, fmaf(dy, dy, dz * dz)));
                            bool ok = !((popA >> t) & 1ull) && (kb < best);
                            best = ok ? kb : best;
                            bj2  = ok ? t * 32 + lane : bj2;
                        }
                        va0 = best; ia0 = bj2;
                    }
                }
            }
        }
    }

    // ---- exactness guard: exactly one owner per pass? ----
    int tot = __reduce_add_sync(FULL, npop);
    if (tot != KNB) {
        slow_row(At, lane, mid, Tn, qx, qy, qz, dist_out, idx_out);
    }
}

// ---------------------------------------------------------------------------
extern "C" void kernel_launch(void* const* d_in, const int* in_sizes, int n_in,
                              void* d_out, int out_size) {
    const float* coords = (const float*)d_in[0];   // (2,256,12,3) f32
    const int*   mask   = (const int*)d_in[1];     // (2,256) i32
    const float* emb    = (const float*)d_in[2];   // (12,32) f32
    const float* scale  = (const float*)d_in[3];   // (1,1,32) f32
    const float* shift  = (const float*)d_in[4];   // (1,1,32) f32
    float* out = (float*)d_out;

    prep_kernel<<<PREP_BLOCKS, 256>>>(coords, mask, emb, scale, shift);

    int nblocks = NROWS / WARPS;                   // 1536
    knn_kernel<<<nblocks, THR>>>(coords, mask, emb, out);
}